// round 1
// baseline (speedup 1.0000x reference)
#include <cuda_runtime.h>
#include <math.h>

// ---------------------------------------------------------------------------
// GraphSAGE 2-layer:  h = relu(mean@Wl1 + bl1 + x@Wr1); out = sigmoid(mean_h@Wl2 + bl2 + h@Wr2)
// Scratch via __device__ globals (no allocation allowed).
// ---------------------------------------------------------------------------

__device__ float g_agg[(size_t)100000 * 128];   // reused for both layers
__device__ float g_h  [(size_t)100000 * 128];
__device__ float g_deg[100000];
__device__ float g_inv[100000];
__device__ int   g_is64;

// ---------------------------------------------------------------------------
__global__ void zero_kernel(float4* p, int n4) {
    int i = blockIdx.x * blockDim.x + threadIdx.x;
    int stride = gridDim.x * blockDim.x;
    float4 z = make_float4(0.f, 0.f, 0.f, 0.f);
    for (; i < n4; i += stride) p[i] = z;
}

// Detect whether edge_index is int64 or int32. Node ids < 100000 < 2^17,
// so for int64 data every odd 32-bit word (high half) is zero.
__global__ void detect_kernel(const int* __restrict__ ei) {
    if (threadIdx.x == 0 && blockIdx.x == 0) {
        int nz = 0;
        for (int i = 1; i < 256; i += 2) nz += (ei[i] != 0);
        g_is64 = (nz == 0) ? 1 : 0;
    }
}

// One warp per edge: gather feat[src] row (512B coalesced), vector-red into agg[dst].
template<bool COUNT>
__global__ void scatter_kernel(const float* __restrict__ feat,
                               const void* __restrict__ ei,
                               float* __restrict__ agg,
                               float* __restrict__ deg,
                               int ne) {
    int gw   = (blockIdx.x * blockDim.x + threadIdx.x) >> 5;
    int lane = threadIdx.x & 31;
    if (gw >= ne) return;

    int s, d;
    if (g_is64) {
        const long long* e64 = (const long long*)ei;
        s = (int)e64[gw];
        d = (int)e64[ne + gw];
    } else {
        const int* e32 = (const int*)ei;
        s = e32[gw];
        d = e32[ne + gw];
    }

    float4 v = reinterpret_cast<const float4*>(feat)[(size_t)s * 32 + lane];
    float* dp = agg + (size_t)d * 128 + lane * 4;
    asm volatile("red.global.add.v4.f32 [%0], {%1,%2,%3,%4};"
                 :: "l"(dp), "f"(v.x), "f"(v.y), "f"(v.z), "f"(v.w)
                 : "memory");
    if (COUNT && lane == 0) atomicAdd(deg + d, 1.0f);
}

__global__ void inv_kernel(const float* __restrict__ deg,
                           float* __restrict__ inv, int n) {
    int i = blockIdx.x * blockDim.x + threadIdx.x;
    if (i < n) inv[i] = 1.0f / fmaxf(deg[i], 1.0f);
}

// ---------------------------------------------------------------------------
// out = act( (agg*inv) @ Wl  +  root @ Wr  + bias )
// A = [mean | root] : [n, 256],  W = [Wl; Wr] : [256, BN]
// BM=64 rows/block, 8x4 register micro-tile per thread.
// ACT: 0 = relu, 1 = sigmoid
// ---------------------------------------------------------------------------
template<int BN, int ACT>
__global__ void __launch_bounds__((64 / 8) * (BN / 4))
sage_gemm(const float* __restrict__ agg,
          const float* __restrict__ inv,
          const float* __restrict__ root,
          const float* __restrict__ Wl,     // [128, BN] row-major
          const float* __restrict__ Wr,     // [128, BN] row-major
          const float* __restrict__ bias,   // [BN]
          float* __restrict__ out,          // [n, BN]
          int n)
{
    constexpr int BM = 64, KT = 32, TM = 8, TN = 4;
    constexpr int TC = BN / TN;           // threads along cols (32 or 16)
    constexpr int NT = (BM / TM) * TC;    // 256 or 128 threads
    constexpr int APAD = 4;               // stride 68: keeps float4 reads aligned

    __shared__ float A_s[KT][BM + APAD];
    __shared__ float W_s[KT][BN];

    const int tid  = threadIdx.x;
    const int tc   = tid % TC;
    const int tr   = tid / TC;
    const int row0 = blockIdx.x * BM;

    float acc[TM][TN];
#pragma unroll
    for (int i = 0; i < TM; i++)
#pragma unroll
        for (int j = 0; j < TN; j++) acc[i][j] = 0.f;

#pragma unroll 1
    for (int kt = 0; kt < 256; kt += KT) {
        const bool first = (kt < 128);
        const float* W = first ? (Wl + kt * BN) : (Wr + (kt - 128) * BN);

        // Load W tile (KT x BN, contiguous) via float4
        for (int i = tid; i < KT * BN / 4; i += NT)
            reinterpret_cast<float4*>(&W_s[0][0])[i] =
                reinterpret_cast<const float4*>(W)[i];

        // Load A tile transposed: A_s[k][row]. Warp reads 32 consecutive k of
        // one row (128B coalesced global read).
#pragma unroll
        for (int c = 0; c < KT * BM; c += NT) {
            int idx  = c + tid;
            int k    = idx & (KT - 1);
            int r    = idx / KT;
            int node = row0 + r;
            float v = 0.f;
            if (node < n) {
                if (first) v = agg [(size_t)node * 128 + kt + k] * inv[node];
                else       v = root[(size_t)node * 128 + (kt - 128) + k];
            }
            A_s[k][r] = v;
        }
        __syncthreads();

#pragma unroll
        for (int k = 0; k < KT; k++) {
            float4 a0 = *reinterpret_cast<const float4*>(&A_s[k][tr * TM]);
            float4 a1 = *reinterpret_cast<const float4*>(&A_s[k][tr * TM + 4]);
            float4 b4 = *reinterpret_cast<const float4*>(&W_s[k][tc * TN]);
            float a[TM] = {a0.x, a0.y, a0.z, a0.w, a1.x, a1.y, a1.z, a1.w};
            float b[TN] = {b4.x, b4.y, b4.z, b4.w};
#pragma unroll
            for (int i = 0; i < TM; i++)
#pragma unroll
                for (int j = 0; j < TN; j++)
                    acc[i][j] = fmaf(a[i], b[j], acc[i][j]);
        }
        __syncthreads();
    }

    float bb[TN];
#pragma unroll
    for (int j = 0; j < TN; j++) bb[j] = bias[tc * TN + j];

#pragma unroll
    for (int i = 0; i < TM; i++) {
        int node = row0 + tr * TM + i;
        if (node < n) {
            float4 o;
            float* ov = reinterpret_cast<float*>(&o);
#pragma unroll
            for (int j = 0; j < TN; j++) {
                float v = acc[i][j] + bb[j];
                if (ACT == 0) v = fmaxf(v, 0.f);
                else          v = 1.0f / (1.0f + __expf(-v));
                ov[j] = v;
            }
            reinterpret_cast<float4*>(out + (size_t)node * BN)[tc] = o;
        }
    }
}

// ---------------------------------------------------------------------------
extern "C" void kernel_launch(void* const* d_in, const int* in_sizes, int n_in,
                              void* d_out, int out_size) {
    const float* x   = (const float*)d_in[0];
    const void*  ei  = d_in[1];
    const float* Wl1 = (const float*)d_in[2];
    const float* bl1 = (const float*)d_in[3];
    const float* Wr1 = (const float*)d_in[4];
    const float* Wl2 = (const float*)d_in[5];
    const float* bl2 = (const float*)d_in[6];
    const float* Wr2 = (const float*)d_in[7];
    float* out = (float*)d_out;

    const int n  = in_sizes[0] / 128;   // 100000
    const int ne = in_sizes[1] / 2;     // 1600000

    float *agg, *h, *deg, *inv;
    cudaGetSymbolAddress((void**)&agg, g_agg);
    cudaGetSymbolAddress((void**)&h,   g_h);
    cudaGetSymbolAddress((void**)&deg, g_deg);
    cudaGetSymbolAddress((void**)&inv, g_inv);

    const int aggN4   = n * 128 / 4;
    const int sblocks = (ne + 7) / 8;          // 8 warps (edges) per block
    const int gblocks = (n + 63) / 64;

    detect_kernel<<<1, 32>>>((const int*)ei);

    // ---- layer 1 ----
    zero_kernel<<<2048, 256>>>((float4*)agg, aggN4);
    zero_kernel<<<128, 256>>>((float4*)deg, n / 4);
    scatter_kernel<true><<<sblocks, 256>>>(x, ei, agg, deg, ne);
    inv_kernel<<<(n + 255) / 256, 256>>>(deg, inv, n);
    sage_gemm<128, 0><<<gblocks, 256>>>(agg, inv, x, Wl1, Wr1, bl1, h, n);

    // ---- layer 2 ----
    zero_kernel<<<2048, 256>>>((float4*)agg, aggN4);
    scatter_kernel<false><<<sblocks, 256>>>(h, ei, agg, nullptr, ne);
    sage_gemm<64, 1><<<gblocks, 128>>>(agg, inv, h, Wl2, Wr2, bl2, out, n);
}

// round 2
// speedup vs baseline: 1.7050x; 1.7050x over previous
#include <cuda_runtime.h>
#include <math.h>

// ---------------------------------------------------------------------------
// GraphSAGE 2-layer via CSR gather-sum (no float atomics):
//   CSR build:  hist(dst) -> 2-level exclusive scan -> fill eidx
//   L1: mean1 = gather_mean(x);  h = relu(mean1@Wl1 + bl1 + x@Wr1)
//   L2: y2 = h@Wl2;  m2 = gather_mean(y2);  out = sigmoid(h@Wr2 + m2 + bl2)
// ---------------------------------------------------------------------------

#define N_MAX 100000
#define E_MAX 1600000

__device__ float g_agg[(size_t)N_MAX * 128];  // mean1; later y2 (lo) + m2 (hi)
__device__ float g_h  [(size_t)N_MAX * 128];
__device__ int   g_cnt[N_MAX];
__device__ int   g_cur[N_MAX];
__device__ int   g_rowptr[N_MAX + 1];
__device__ int   g_eidx[E_MAX];
__device__ int   g_bsum[256];
__device__ int   g_boff[256];
__device__ int   g_is64;

// ---------------------------------------------------------------------------
__global__ void detect_kernel(const int* __restrict__ ei) {
    if (threadIdx.x == 0 && blockIdx.x == 0) {
        int nz = 0;
        for (int i = 1; i < 256; i += 2) nz += (ei[i] != 0);
        g_is64 = (nz == 0) ? 1 : 0;
    }
}

__device__ __forceinline__ int edge_at(const void* ei, long long idx, int is64) {
    if (is64) return (int)((const long long*)ei)[idx];
    return ((const int*)ei)[idx];
}

__global__ void zero_int_kernel(int* p, int n) {
    int i = blockIdx.x * blockDim.x + threadIdx.x;
    if (i < n) p[i] = 0;
}

__global__ void hist_kernel(const void* __restrict__ ei, int* __restrict__ cnt, int ne) {
    int i = blockIdx.x * blockDim.x + threadIdx.x;
    int is64 = g_is64;
    if (i < ne) {
        int d = edge_at(ei, (long long)ne + i, is64);
        atomicAdd(&cnt[d], 1);
    }
}

// block partial sums (196 blocks x 512)
__global__ void blocksum_kernel(const int* __restrict__ cnt, int* __restrict__ bsum, int n) {
    __shared__ int sh[512];
    int i = blockIdx.x * 512 + threadIdx.x;
    sh[threadIdx.x] = (i < n) ? cnt[i] : 0;
    __syncthreads();
    for (int off = 256; off > 0; off >>= 1) {
        if (threadIdx.x < off) sh[threadIdx.x] += sh[threadIdx.x + off];
        __syncthreads();
    }
    if (threadIdx.x == 0) bsum[blockIdx.x] = sh[0];
}

// exclusive scan of <=256 block sums in one block
__global__ void scanbsum_kernel(const int* __restrict__ bsum, int* __restrict__ boff,
                                int* __restrict__ rowptr, int nb, int n, int ne) {
    __shared__ int sh[256];
    int tid = threadIdx.x;
    int v = (tid < nb) ? bsum[tid] : 0;
    sh[tid] = v;
    __syncthreads();
    for (int off = 1; off < 256; off <<= 1) {
        int t = (tid >= off) ? sh[tid - off] : 0;
        __syncthreads();
        sh[tid] += t;
        __syncthreads();
    }
    if (tid < nb) boff[tid] = sh[tid] - v;
    if (tid == 0) rowptr[n] = ne;
}

// in-block exclusive scan + add block offset -> rowptr & cursor
__global__ void scatter_scan_kernel(const int* __restrict__ cnt,
                                    const int* __restrict__ boff,
                                    int* __restrict__ rowptr,
                                    int* __restrict__ cur, int n) {
    __shared__ int sh[512];
    int tid = threadIdx.x;
    int i = blockIdx.x * 512 + tid;
    int v = (i < n) ? cnt[i] : 0;
    sh[tid] = v;
    __syncthreads();
    for (int off = 1; off < 512; off <<= 1) {
        int t = (tid >= off) ? sh[tid - off] : 0;
        __syncthreads();
        sh[tid] += t;
        __syncthreads();
    }
    int excl = sh[tid] - v + boff[blockIdx.x];
    if (i < n) { rowptr[i] = excl; cur[i] = excl; }
}

__global__ void fill_kernel(const void* __restrict__ ei, int* __restrict__ cur,
                            int* __restrict__ eidx, int ne) {
    int i = blockIdx.x * blockDim.x + threadIdx.x;
    int is64 = g_is64;
    if (i < ne) {
        int s = edge_at(ei, i, is64);
        int d = edge_at(ei, (long long)ne + i, is64);
        int pos = atomicAdd(&cur[d], 1);
        eidx[pos] = s;
    }
}

// ---------------------------------------------------------------------------
// gather-mean, 128-wide features: one warp per node, float4 per lane.
__global__ void gather_mean128(const float* __restrict__ feat,
                               const int* __restrict__ rowptr,
                               const int* __restrict__ eidx,
                               float* __restrict__ mean, int n) {
    int node = (blockIdx.x * blockDim.x + threadIdx.x) >> 5;
    if (node >= n) return;
    int lane = threadIdx.x & 31;
    int beg = rowptr[node], end = rowptr[node + 1];
    float4 acc = make_float4(0.f, 0.f, 0.f, 0.f);
    int j = beg;
    for (; j + 1 < end; j += 2) {
        int s0 = __ldg(&eidx[j]);
        int s1 = __ldg(&eidx[j + 1]);
        float4 v0 = __ldg((const float4*)feat + (size_t)s0 * 32 + lane);
        float4 v1 = __ldg((const float4*)feat + (size_t)s1 * 32 + lane);
        acc.x += v0.x; acc.y += v0.y; acc.z += v0.z; acc.w += v0.w;
        acc.x += v1.x; acc.y += v1.y; acc.z += v1.z; acc.w += v1.w;
    }
    if (j < end) {
        int s0 = __ldg(&eidx[j]);
        float4 v0 = __ldg((const float4*)feat + (size_t)s0 * 32 + lane);
        acc.x += v0.x; acc.y += v0.y; acc.z += v0.z; acc.w += v0.w;
    }
    float inv = 1.0f / fmaxf((float)(end - beg), 1.0f);
    acc.x *= inv; acc.y *= inv; acc.z *= inv; acc.w *= inv;
    ((float4*)mean)[(size_t)node * 32 + lane] = acc;
}

// gather-mean, 64-wide features: one warp per node, float2 per lane.
__global__ void gather_mean64(const float* __restrict__ feat,
                              const int* __restrict__ rowptr,
                              const int* __restrict__ eidx,
                              float* __restrict__ mean, int n) {
    int node = (blockIdx.x * blockDim.x + threadIdx.x) >> 5;
    if (node >= n) return;
    int lane = threadIdx.x & 31;
    int beg = rowptr[node], end = rowptr[node + 1];
    float2 acc = make_float2(0.f, 0.f);
    int j = beg;
    for (; j + 1 < end; j += 2) {
        int s0 = __ldg(&eidx[j]);
        int s1 = __ldg(&eidx[j + 1]);
        float2 v0 = __ldg((const float2*)feat + (size_t)s0 * 32 + lane);
        float2 v1 = __ldg((const float2*)feat + (size_t)s1 * 32 + lane);
        acc.x += v0.x; acc.y += v0.y;
        acc.x += v1.x; acc.y += v1.y;
    }
    if (j < end) {
        int s0 = __ldg(&eidx[j]);
        float2 v0 = __ldg((const float2*)feat + (size_t)s0 * 32 + lane);
        acc.x += v0.x; acc.y += v0.y;
    }
    float inv = 1.0f / fmaxf((float)(end - beg), 1.0f);
    acc.x *= inv; acc.y *= inv;
    ((float2*)mean)[(size_t)node * 32 + lane] = acc;
}

// ---------------------------------------------------------------------------
// C = act( A0@W0 [+ A1@W1] [+ addv] [+ bias] )
// A0,A1: [n,128]; W: [128,BN] row-major. BM=128, TM=8, 256 threads.
// ACT: 0 none, 1 relu, 2 sigmoid
// ---------------------------------------------------------------------------
template<int BN, int TN, int HAS_A1, int ACT, int HAS_ADD, int HAS_BIAS>
__global__ void __launch_bounds__(256)
gemm_kernel(const float* __restrict__ A0,
            const float* __restrict__ A1,
            const float* __restrict__ W0,
            const float* __restrict__ W1,
            const float* __restrict__ bias,
            const float* __restrict__ addv,
            float* __restrict__ out,
            int n)
{
    constexpr int BM = 128, KT = 32, TM = 8;
    constexpr int TC = BN / TN;               // 16
    constexpr int KTOT = HAS_A1 ? 256 : 128;

    __shared__ float A_s[KT][BM + 4];
    __shared__ float W_s[KT][BN];

    const int tid  = threadIdx.x;
    const int tc   = tid % TC;
    const int tr   = tid / TC;
    const int row0 = blockIdx.x * BM;

    float acc[TM][TN];
#pragma unroll
    for (int i = 0; i < TM; i++)
#pragma unroll
        for (int j = 0; j < TN; j++) acc[i][j] = 0.f;

#pragma unroll 1
    for (int kt = 0; kt < KTOT; kt += KT) {
        const float* Asrc = (HAS_A1 && kt >= 128) ? A1 : A0;
        const float* Wsrc = (HAS_A1 && kt >= 128) ? W1 : W0;
        const int kk = kt & 127;

        // W tile: KT x BN contiguous
#pragma unroll
        for (int i = tid; i < KT * BN / 4; i += 256)
            ((float4*)&W_s[0][0])[i] = ((const float4*)(Wsrc + kk * BN))[i];

        // A tile transposed: warp reads 32 consecutive k of one row (128B line)
#pragma unroll
        for (int c = 0; c < KT * BM; c += 256) {
            int idx = c + tid;
            int k = idx & (KT - 1);
            int r = idx >> 5;
            int node = row0 + r;
            A_s[k][r] = (node < n) ? Asrc[(size_t)node * 128 + kk + k] : 0.f;
        }
        __syncthreads();

#pragma unroll 4
        for (int k = 0; k < KT; k++) {
            float a[TM], b[TN];
            *(float4*)&a[0] = *(const float4*)&A_s[k][tr * TM];
            *(float4*)&a[4] = *(const float4*)&A_s[k][tr * TM + 4];
#pragma unroll
            for (int j = 0; j < TN; j += 4)
                *(float4*)&b[j] = *(const float4*)&W_s[k][tc * TN + j];
#pragma unroll
            for (int i = 0; i < TM; i++)
#pragma unroll
                for (int j = 0; j < TN; j++)
                    acc[i][j] = fmaf(a[i], b[j], acc[i][j]);
        }
        __syncthreads();
    }

    float bb[TN];
#pragma unroll
    for (int j = 0; j < TN; j++) bb[j] = HAS_BIAS ? bias[tc * TN + j] : 0.f;

#pragma unroll
    for (int i = 0; i < TM; i++) {
        int node = row0 + tr * TM + i;
        if (node < n) {
#pragma unroll
            for (int j4 = 0; j4 < TN; j4 += 4) {
                float4 ad;
                if (HAS_ADD)
                    ad = __ldg((const float4*)(addv + (size_t)node * BN + tc * TN + j4));
                float4 o;
                float* ov = (float*)&o;
                const float* av = (const float*)&ad;
#pragma unroll
                for (int j = 0; j < 4; j++) {
                    float v = acc[i][j4 + j] + bb[j4 + j];
                    if (HAS_ADD) v += av[j];
                    if (ACT == 1) v = fmaxf(v, 0.f);
                    if (ACT == 2) v = 1.0f / (1.0f + __expf(-v));
                    ov[j] = v;
                }
                *(float4*)(out + (size_t)node * BN + tc * TN + j4) = o;
            }
        }
    }
}

// ---------------------------------------------------------------------------
extern "C" void kernel_launch(void* const* d_in, const int* in_sizes, int n_in,
                              void* d_out, int out_size) {
    const float* x   = (const float*)d_in[0];
    const void*  ei  = d_in[1];
    const float* Wl1 = (const float*)d_in[2];
    const float* bl1 = (const float*)d_in[3];
    const float* Wr1 = (const float*)d_in[4];
    const float* Wl2 = (const float*)d_in[5];
    const float* bl2 = (const float*)d_in[6];
    const float* Wr2 = (const float*)d_in[7];
    float* out = (float*)d_out;

    const int n  = in_sizes[0] / 128;   // 100000
    const int ne = in_sizes[1] / 2;     // 1600000

    float *agg, *h;
    int *cnt, *cur, *rowptr, *eidx, *bsum, *boff;
    cudaGetSymbolAddress((void**)&agg,    g_agg);
    cudaGetSymbolAddress((void**)&h,      g_h);
    cudaGetSymbolAddress((void**)&cnt,    g_cnt);
    cudaGetSymbolAddress((void**)&cur,    g_cur);
    cudaGetSymbolAddress((void**)&rowptr, g_rowptr);
    cudaGetSymbolAddress((void**)&eidx,   g_eidx);
    cudaGetSymbolAddress((void**)&bsum,   g_bsum);
    cudaGetSymbolAddress((void**)&boff,   g_boff);

    float* y2 = agg;                       // [n,64]
    float* m2 = agg + (size_t)n * 64;      // [n,64]

    const int nscan = (n + 511) / 512;     // 196
    const int eblk  = (ne + 255) / 256;
    const int gblk  = (n + 7) / 8;         // 8 warps/block gather
    const int mblk  = (n + 127) / 128;     // GEMM blocks

    // ---- CSR build (once, shared by both layers) ----
    detect_kernel<<<1, 32>>>((const int*)ei);
    zero_int_kernel<<<(n + 255) / 256, 256>>>(cnt, n);
    hist_kernel<<<eblk, 256>>>(ei, cnt, ne);
    blocksum_kernel<<<nscan, 512>>>(cnt, bsum, n);
    scanbsum_kernel<<<1, 256>>>(bsum, boff, rowptr, nscan, n, ne);
    scatter_scan_kernel<<<nscan, 512>>>(cnt, boff, rowptr, cur, n);
    fill_kernel<<<eblk, 256>>>(ei, cur, eidx, ne);

    // ---- layer 1: mean1 -> h ----
    gather_mean128<<<gblk, 256>>>(x, rowptr, eidx, agg, n);
    gemm_kernel<128, 8, 1, 1, 0, 1><<<mblk, 256>>>(agg, x, Wl1, Wr1, bl1, nullptr, h, n);

    // ---- layer 2: y2 = h@Wl2; m2 = mean(y2); out = sigmoid(h@Wr2 + m2 + bl2) ----
    gemm_kernel<64, 4, 0, 0, 0, 0><<<mblk, 256>>>(h, nullptr, Wl2, nullptr, nullptr, nullptr, y2, n);
    gather_mean64<<<gblk, 256>>>(y2, rowptr, eidx, m2, n);
    gemm_kernel<64, 4, 0, 2, 1, 1><<<mblk, 256>>>(h, nullptr, Wr2, nullptr, bl2, m2, out, n);
}

// round 4
// speedup vs baseline: 2.7218x; 1.5963x over previous
#include <cuda_runtime.h>
#include <cstdint>
#include <math.h>

// ---------------------------------------------------------------------------
// GraphSAGE 2-layer. CSR gather-mean + TF32 mma.sync GEMMs (arch-stable PTX).
//   L1: mean1 = gmean(x);  h = relu([mean1|x] @ W1t^T + bl1)
//   L2: y2full = h @ [Wl2|Wr2];  m2 = gmean(y2full[:, :64]);
//       out = sigmoid(y2full[:,64:] + m2 + bl2)
// ---------------------------------------------------------------------------

#define N_MAX 100000
#define E_MAX 1600000

__device__ float g_mean[(size_t)N_MAX * 128];   // mean1, then y2full
__device__ float g_h  [(size_t)N_MAX * 128];
__device__ float g_m2 [(size_t)N_MAX * 64];
__device__ float g_w1t[128 * 256];              // [N=128, K=256] K-major
__device__ float g_w2t[128 * 128];              // [N=128, K=128] K-major
__device__ int   g_cnt[N_MAX];
__device__ int   g_cur[N_MAX];
__device__ int   g_rowptr[N_MAX + 1];
__device__ int   g_eidx[E_MAX];
__device__ int   g_bsum[256];
__device__ int   g_boff[256];
__device__ int   g_is64;

// ---------------- helpers ----------------
__device__ __forceinline__ uint32_t f2tf32(float x) {
    uint32_t r;
    asm("cvt.rna.tf32.f32 %0, %1;" : "=r"(r) : "f"(x));
    return r;
}
__device__ __forceinline__ void mma_tf32(float (&c)[4], const uint32_t (&a)[4],
                                         const uint32_t (&b)[2]) {
    asm volatile(
        "mma.sync.aligned.m16n8k8.row.col.f32.tf32.tf32.f32 "
        "{%0,%1,%2,%3}, {%4,%5,%6,%7}, {%8,%9}, {%0,%1,%2,%3};"
        : "+f"(c[0]), "+f"(c[1]), "+f"(c[2]), "+f"(c[3])
        : "r"(a[0]), "r"(a[1]), "r"(a[2]), "r"(a[3]), "r"(b[0]), "r"(b[1]));
}

// ---------------- CSR build ----------------
__global__ void detect_kernel(const int* __restrict__ ei) {
    if (threadIdx.x == 0 && blockIdx.x == 0) {
        int nz = 0;
        for (int i = 1; i < 256; i += 2) nz += (ei[i] != 0);
        g_is64 = (nz == 0) ? 1 : 0;
    }
}
__device__ __forceinline__ int edge_at(const void* ei, long long idx, int is64) {
    if (is64) return (int)((const long long*)ei)[idx];
    return ((const int*)ei)[idx];
}
__global__ void zero_int_kernel(int* p, int n) {
    int i = blockIdx.x * blockDim.x + threadIdx.x;
    if (i < n) p[i] = 0;
}
__global__ void hist_kernel(const void* __restrict__ ei, int* __restrict__ cnt, int ne) {
    int i = blockIdx.x * blockDim.x + threadIdx.x;
    int is64 = g_is64;
    if (i < ne) atomicAdd(&cnt[edge_at(ei, (long long)ne + i, is64)], 1);
}
__global__ void blocksum_kernel(const int* __restrict__ cnt, int* __restrict__ bsum, int n) {
    __shared__ int sh[512];
    int i = blockIdx.x * 512 + threadIdx.x;
    sh[threadIdx.x] = (i < n) ? cnt[i] : 0;
    __syncthreads();
    for (int off = 256; off > 0; off >>= 1) {
        if (threadIdx.x < off) sh[threadIdx.x] += sh[threadIdx.x + off];
        __syncthreads();
    }
    if (threadIdx.x == 0) bsum[blockIdx.x] = sh[0];
}
__global__ void scanbsum_kernel(const int* __restrict__ bsum, int* __restrict__ boff,
                                int* __restrict__ rowptr, int nb, int n, int ne) {
    __shared__ int sh[256];
    int tid = threadIdx.x;
    int v = (tid < nb) ? bsum[tid] : 0;
    sh[tid] = v;
    __syncthreads();
    for (int off = 1; off < 256; off <<= 1) {
        int t = (tid >= off) ? sh[tid - off] : 0;
        __syncthreads();
        sh[tid] += t;
        __syncthreads();
    }
    if (tid < nb) boff[tid] = sh[tid] - v;
    if (tid == 0) rowptr[n] = ne;
}
__global__ void scatter_scan_kernel(const int* __restrict__ cnt, const int* __restrict__ boff,
                                    int* __restrict__ rowptr, int* __restrict__ cur, int n) {
    __shared__ int sh[512];
    int tid = threadIdx.x;
    int i = blockIdx.x * 512 + tid;
    int v = (i < n) ? cnt[i] : 0;
    sh[tid] = v;
    __syncthreads();
    for (int off = 1; off < 512; off <<= 1) {
        int t = (tid >= off) ? sh[tid - off] : 0;
        __syncthreads();
        sh[tid] += t;
        __syncthreads();
    }
    int excl = sh[tid] - v + boff[blockIdx.x];
    if (i < n) { rowptr[i] = excl; cur[i] = excl; }
}
__global__ void fill_kernel(const void* __restrict__ ei, int* __restrict__ cur,
                            int* __restrict__ eidx, int ne) {
    int i = blockIdx.x * blockDim.x + threadIdx.x;
    int is64 = g_is64;
    if (i < ne) {
        int s = edge_at(ei, i, is64);
        int d = edge_at(ei, (long long)ne + i, is64);
        eidx[atomicAdd(&cur[d], 1)] = s;
    }
}

// ---------------- weight transposes ----------------
__global__ void transpose_w1(const float* __restrict__ Wl1, const float* __restrict__ Wr1,
                             float* __restrict__ W1t) {
    int i = blockIdx.x * blockDim.x + threadIdx.x;     // 128*256
    if (i < 128 * 256) {
        int nn = i >> 8, k = i & 255;
        W1t[i] = (k < 128) ? Wl1[k * 128 + nn] : Wr1[(k - 128) * 128 + nn];
    }
}
__global__ void transpose_w2(const float* __restrict__ Wl2, const float* __restrict__ Wr2,
                             float* __restrict__ W2t) {
    int i = blockIdx.x * blockDim.x + threadIdx.x;     // 128*128
    if (i < 128 * 128) {
        int nn = i >> 7, k = i & 127;
        W2t[i] = (nn < 64) ? Wl2[k * 64 + nn] : Wr2[k * 64 + (nn - 64)];
    }
}

// ---------------- gather means ----------------
__global__ void gather_mean128(const float* __restrict__ feat, const int* __restrict__ rowptr,
                               const int* __restrict__ eidx, float* __restrict__ mean, int n) {
    int node = (blockIdx.x * blockDim.x + threadIdx.x) >> 5;
    if (node >= n) return;
    int lane = threadIdx.x & 31;
    int beg = rowptr[node], end = rowptr[node + 1];
    float4 acc = make_float4(0.f, 0.f, 0.f, 0.f);
    int j = beg;
    for (; j + 1 < end; j += 2) {
        int s0 = __ldg(&eidx[j]), s1 = __ldg(&eidx[j + 1]);
        float4 v0 = __ldg((const float4*)feat + (size_t)s0 * 32 + lane);
        float4 v1 = __ldg((const float4*)feat + (size_t)s1 * 32 + lane);
        acc.x += v0.x + v1.x; acc.y += v0.y + v1.y;
        acc.z += v0.z + v1.z; acc.w += v0.w + v1.w;
    }
    if (j < end) {
        int s0 = __ldg(&eidx[j]);
        float4 v0 = __ldg((const float4*)feat + (size_t)s0 * 32 + lane);
        acc.x += v0.x; acc.y += v0.y; acc.z += v0.z; acc.w += v0.w;
    }
    float inv = 1.0f / fmaxf((float)(end - beg), 1.0f);
    acc.x *= inv; acc.y *= inv; acc.z *= inv; acc.w *= inv;
    ((float4*)mean)[(size_t)node * 32 + lane] = acc;
}

// gather cols [0,64) of y2full (row stride 128 floats); m2 compact [n,64]
__global__ void gather_mean64s(const float* __restrict__ feat, const int* __restrict__ rowptr,
                               const int* __restrict__ eidx, float* __restrict__ m2, int n) {
    int node = (blockIdx.x * blockDim.x + threadIdx.x) >> 5;
    if (node >= n) return;
    int lane = threadIdx.x & 31;
    int beg = rowptr[node], end = rowptr[node + 1];
    float2 acc = make_float2(0.f, 0.f);
    int j = beg;
    for (; j + 1 < end; j += 2) {
        int s0 = __ldg(&eidx[j]), s1 = __ldg(&eidx[j + 1]);
        float2 v0 = __ldg((const float2*)feat + (size_t)s0 * 64 + lane);
        float2 v1 = __ldg((const float2*)feat + (size_t)s1 * 64 + lane);
        acc.x += v0.x + v1.x; acc.y += v0.y + v1.y;
    }
    if (j < end) {
        int s0 = __ldg(&eidx[j]);
        float2 v0 = __ldg((const float2*)feat + (size_t)s0 * 64 + lane);
        acc.x += v0.x; acc.y += v0.y;
    }
    float inv = 1.0f / fmaxf((float)(end - beg), 1.0f);
    acc.x *= inv; acc.y *= inv;
    ((float2*)m2)[(size_t)node * 32 + lane] = acc;
}

// ---------------------------------------------------------------------------
// TF32 mma.sync GEMM: C[128-tile, 128] = A[*, KTOT] @ Wt^T  (Wt: [128, KTOT])
// Block 128x128, 8 warps in 2(m) x 4(n); warp tile 64x32; mma m16n8k8.
// EPI: 1 = relu(c + bias); 0 = raw
// ---------------------------------------------------------------------------
template<int KTOT, int HAS_A1, int EPI>
__global__ void __launch_bounds__(256, 2)
mma_gemm(const float* __restrict__ A0, const float* __restrict__ A1,
         const float* __restrict__ Wt, const float* __restrict__ bias,
         float* __restrict__ out, int n)
{
    constexpr int NCHUNK = KTOT / 32;
    __shared__ uint32_t As[128][36];   // [m][k] tf32 bits, pad 4
    __shared__ uint32_t Ws[128][36];   // [n][k] tf32 bits

    const int tid  = threadIdx.x;
    const int wid  = tid >> 5;
    const int lane = tid & 31;
    const int wm   = wid & 1;          // 0..1  (64-row slabs)
    const int wn   = wid >> 1;         // 0..3  (32-col slabs)
    const int g    = lane >> 2;        // 0..7
    const int tg   = lane & 3;         // 0..3
    const int row0 = blockIdx.x * 128;

    float c[4][4][4];
#pragma unroll
    for (int mi = 0; mi < 4; mi++)
#pragma unroll
        for (int ni = 0; ni < 4; ni++)
#pragma unroll
            for (int j = 0; j < 4; j++) c[mi][ni][j] = 0.f;

#pragma unroll 1
    for (int ch = 0; ch < NCHUNK; ++ch) {
        const int kcol = ch * 32;
        const float* Asrc = A0;
        int kk = kcol;
        if (HAS_A1 && kcol >= 128) { Asrc = A1; kk = kcol - 128; }

        // Load + convert A and W tiles (128 x 32 each). Threads cover rows in
        // groups of 8 (one row = 32 floats = 8 threads x float4): coalesced.
#pragma unroll
        for (int i = tid; i < 1024; i += 256) {
            int r  = i >> 3;
            int k4 = (i & 7) * 4;
            int node = row0 + r;
            float4 av = make_float4(0.f, 0.f, 0.f, 0.f);
            if (node < n)
                av = *(const float4*)(Asrc + (size_t)node * 128 + kk + k4);
            uint4 at;
            at.x = f2tf32(av.x); at.y = f2tf32(av.y);
            at.z = f2tf32(av.z); at.w = f2tf32(av.w);
            *(uint4*)&As[r][k4] = at;

            float4 wv = *(const float4*)(Wt + (size_t)r * KTOT + kcol + k4);
            uint4 wt;
            wt.x = f2tf32(wv.x); wt.y = f2tf32(wv.y);
            wt.z = f2tf32(wv.z); wt.w = f2tf32(wv.w);
            *(uint4*)&Ws[r][k4] = wt;
        }
        __syncthreads();

#pragma unroll
        for (int ks = 0; ks < 4; ++ks) {
            const int k0 = ks * 8;
            uint32_t a[4][4];
#pragma unroll
            for (int mi = 0; mi < 4; mi++) {
                int mb = wm * 64 + mi * 16;
                a[mi][0] = As[mb + g][k0 + tg];
                a[mi][1] = As[mb + g + 8][k0 + tg];
                a[mi][2] = As[mb + g][k0 + tg + 4];
                a[mi][3] = As[mb + g + 8][k0 + tg + 4];
            }
#pragma unroll
            for (int ni = 0; ni < 4; ni++) {
                int nb = wn * 32 + ni * 8 + g;
                uint32_t b[2];
                b[0] = Ws[nb][k0 + tg];
                b[1] = Ws[nb][k0 + tg + 4];
#pragma unroll
                for (int mi = 0; mi < 4; mi++)
                    mma_tf32(c[mi][ni], a[mi], b);
            }
        }
        __syncthreads();
    }

    // epilogue: thread owns rows {g, g+8} (+16*mi +64*wm), col pairs tg*2 (+8*ni +32*wn)
#pragma unroll
    for (int mi = 0; mi < 4; mi++) {
#pragma unroll
        for (int half = 0; half < 2; half++) {
            int row = row0 + wm * 64 + mi * 16 + g + half * 8;
            if (row < n) {
#pragma unroll
                for (int ni = 0; ni < 4; ni++) {
                    int col = wn * 32 + ni * 8 + tg * 2;
                    float v0 = c[mi][ni][half * 2 + 0];
                    float v1 = c[mi][ni][half * 2 + 1];
                    if (EPI == 1) {
                        v0 = fmaxf(v0 + __ldg(&bias[col]), 0.f);
                        v1 = fmaxf(v1 + __ldg(&bias[col + 1]), 0.f);
                    }
                    float2 o = make_float2(v0, v1);
                    *(float2*)(out + (size_t)row * 128 + col) = o;
                }
            }
        }
    }
}

// ---------------- final elementwise ----------------
__global__ void final_kernel(const float* __restrict__ y2full, const float* __restrict__ m2,
                             const float* __restrict__ bl2, float* __restrict__ out, int n) {
    int i = blockIdx.x * blockDim.x + threadIdx.x;   // over n*16 float4s
    if (i >= n * 16) return;
    int node = i >> 4, j4 = i & 15;
    float4 a = *(const float4*)(y2full + (size_t)node * 128 + 64 + j4 * 4);
    float4 b = *(const float4*)(m2 + (size_t)node * 64 + j4 * 4);
    float4 c = *(const float4*)(bl2 + j4 * 4);
    float4 o;
    o.x = 1.0f / (1.0f + __expf(-(a.x + b.x + c.x)));
    o.y = 1.0f / (1.0f + __expf(-(a.y + b.y + c.y)));
    o.z = 1.0f / (1.0f + __expf(-(a.z + b.z + c.z)));
    o.w = 1.0f / (1.0f + __expf(-(a.w + b.w + c.w)));
    *(float4*)(out + (size_t)node * 64 + j4 * 4) = o;
}

// ---------------------------------------------------------------------------
extern "C" void kernel_launch(void* const* d_in, const int* in_sizes, int n_in,
                              void* d_out, int out_size) {
    const float* x   = (const float*)d_in[0];
    const void*  ei  = d_in[1];
    const float* Wl1 = (const float*)d_in[2];
    const float* bl1 = (const float*)d_in[3];
    const float* Wr1 = (const float*)d_in[4];
    const float* Wl2 = (const float*)d_in[5];
    const float* bl2 = (const float*)d_in[6];
    const float* Wr2 = (const float*)d_in[7];
    float* out = (float*)d_out;

    const int n  = in_sizes[0] / 128;   // 100000
    const int ne = in_sizes[1] / 2;     // 1600000

    float *mean, *h, *m2, *w1t, *w2t;
    int *cnt, *cur, *rowptr, *eidx, *bsum, *boff;
    cudaGetSymbolAddress((void**)&mean,   g_mean);
    cudaGetSymbolAddress((void**)&h,      g_h);
    cudaGetSymbolAddress((void**)&m2,     g_m2);
    cudaGetSymbolAddress((void**)&w1t,    g_w1t);
    cudaGetSymbolAddress((void**)&w2t,    g_w2t);
    cudaGetSymbolAddress((void**)&cnt,    g_cnt);
    cudaGetSymbolAddress((void**)&cur,    g_cur);
    cudaGetSymbolAddress((void**)&rowptr, g_rowptr);
    cudaGetSymbolAddress((void**)&eidx,   g_eidx);
    cudaGetSymbolAddress((void**)&bsum,   g_bsum);
    cudaGetSymbolAddress((void**)&boff,   g_boff);

    const int nscan = (n + 511) / 512;
    const int eblk  = (ne + 255) / 256;
    const int gblk  = (n + 7) / 8;
    const int mblk  = (n + 127) / 128;   // 782 GEMM tiles

    // ---- CSR build + weight transposes ----
    detect_kernel<<<1, 32>>>((const int*)ei);
    transpose_w1<<<(128 * 256 + 255) / 256, 256>>>(Wl1, Wr1, w1t);
    transpose_w2<<<(128 * 128 + 255) / 256, 256>>>(Wl2, Wr2, w2t);
    zero_int_kernel<<<(n + 255) / 256, 256>>>(cnt, n);
    hist_kernel<<<eblk, 256>>>(ei, cnt, ne);
    blocksum_kernel<<<nscan, 512>>>(cnt, bsum, n);
    scanbsum_kernel<<<1, 256>>>(bsum, boff, rowptr, nscan, n, ne);
    scatter_scan_kernel<<<nscan, 512>>>(cnt, boff, rowptr, cur, n);
    fill_kernel<<<eblk, 256>>>(ei, cur, eidx, ne);

    // ---- layer 1 ----
    gather_mean128<<<gblk, 256>>>(x, rowptr, eidx, mean, n);
    mma_gemm<256, 1, 1><<<mblk, 256>>>(mean, x, w1t, bl1, h, n);

    // ---- layer 2 ----  (y2full reuses `mean` buffer)
    mma_gemm<128, 0, 0><<<mblk, 256>>>(h, nullptr, w2t, nullptr, mean, n);
    gather_mean64s<<<gblk, 256>>>(mean, rowptr, eidx, m2, n);
    final_kernel<<<(n * 16 + 255) / 256, 256>>>(mean, m2, bl2, out, n);
}

// round 5
// speedup vs baseline: 2.8036x; 1.0301x over previous
#include <cuda_runtime.h>
#include <cuda_bf16.h>
#include <cstdint>
#include <math.h>

// ---------------------------------------------------------------------------
// GraphSAGE 2-layer. CSR gather-mean (bf16 payload, f32 accum) + TF32 mma.sync.
//   L1: xb = bf16(x); mean1 = gmean(xb); h = relu([mean1|x] @ W1t^T + bl1)
//   L2: [y2b(bf16) | y2hi(f32)] = h @ [Wl2|Wr2]
//       out = sigmoid(y2hi + gmean(y2b) + bl2)      (fused gather+final)
// ---------------------------------------------------------------------------

#define N_MAX 100000
#define E_MAX 1600000

__device__ float    g_mean[(size_t)N_MAX * 128];
__device__ float    g_h   [(size_t)N_MAX * 128];
__device__ float    g_y2hi[(size_t)N_MAX * 64];
__device__ uint16_t g_xb  [(size_t)N_MAX * 128];   // bf16 bits
__device__ uint16_t g_y2b [(size_t)N_MAX * 64];    // bf16 bits
__device__ float    g_w1t[128 * 256];              // [N=128, K=256] K-major
__device__ float    g_w2t[128 * 128];              // [N=128, K=128] K-major
__device__ int      g_cnt[N_MAX];
__device__ int      g_cur[N_MAX];
__device__ int      g_rowptr[N_MAX + 1];
__device__ int      g_eidx[E_MAX];
__device__ int      g_bsum[256];
__device__ int      g_boff[256];
__device__ int      g_is64;

// ---------------- helpers ----------------
__device__ __forceinline__ uint32_t f2tf32(float x) {
    uint32_t r;
    asm("cvt.rna.tf32.f32 %0, %1;" : "=r"(r) : "f"(x));
    return r;
}
__device__ __forceinline__ void mma_tf32(float (&c)[4], const uint32_t (&a)[4],
                                         const uint32_t (&b)[2]) {
    asm volatile(
        "mma.sync.aligned.m16n8k8.row.col.f32.tf32.tf32.f32 "
        "{%0,%1,%2,%3}, {%4,%5,%6,%7}, {%8,%9}, {%0,%1,%2,%3};"
        : "+f"(c[0]), "+f"(c[1]), "+f"(c[2]), "+f"(c[3])
        : "r"(a[0]), "r"(a[1]), "r"(a[2]), "r"(a[3]), "r"(b[0]), "r"(b[1]));
}
__device__ __forceinline__ float2 bf2_to_f2(uint32_t v) {
    __nv_bfloat162 b = *reinterpret_cast<__nv_bfloat162*>(&v);
    return __bfloat1622float2(b);
}
__device__ __forceinline__ uint32_t f2_to_bf2(float lo, float hi) {
    __nv_bfloat162 b = __floats2bfloat162_rn(lo, hi);
    return *reinterpret_cast<uint32_t*>(&b);
}

// ---------------- CSR build ----------------
__global__ void detect_kernel(const int* __restrict__ ei) {
    if (threadIdx.x == 0 && blockIdx.x == 0) {
        int nz = 0;
        for (int i = 1; i < 256; i += 2) nz += (ei[i] != 0);
        g_is64 = (nz == 0) ? 1 : 0;
    }
}
__device__ __forceinline__ int edge_at(const void* ei, long long idx, int is64) {
    if (is64) return (int)((const long long*)ei)[idx];
    return ((const int*)ei)[idx];
}
__global__ void zero_int_kernel(int* p, int n) {
    int i = blockIdx.x * blockDim.x + threadIdx.x;
    if (i < n) p[i] = 0;
}
__global__ void hist_kernel(const void* __restrict__ ei, int* __restrict__ cnt, int ne) {
    int i = blockIdx.x * blockDim.x + threadIdx.x;
    int is64 = g_is64;
    if (i < ne) atomicAdd(&cnt[edge_at(ei, (long long)ne + i, is64)], 1);
}
__global__ void blocksum_kernel(const int* __restrict__ cnt, int* __restrict__ bsum, int n) {
    __shared__ int sh[512];
    int i = blockIdx.x * 512 + threadIdx.x;
    sh[threadIdx.x] = (i < n) ? cnt[i] : 0;
    __syncthreads();
    for (int off = 256; off > 0; off >>= 1) {
        if (threadIdx.x < off) sh[threadIdx.x] += sh[threadIdx.x + off];
        __syncthreads();
    }
    if (threadIdx.x == 0) bsum[blockIdx.x] = sh[0];
}
__global__ void scanbsum_kernel(const int* __restrict__ bsum, int* __restrict__ boff,
                                int* __restrict__ rowptr, int nb, int n, int ne) {
    __shared__ int sh[256];
    int tid = threadIdx.x;
    int v = (tid < nb) ? bsum[tid] : 0;
    sh[tid] = v;
    __syncthreads();
    for (int off = 1; off < 256; off <<= 1) {
        int t = (tid >= off) ? sh[tid - off] : 0;
        __syncthreads();
        sh[tid] += t;
        __syncthreads();
    }
    if (tid < nb) boff[tid] = sh[tid] - v;
    if (tid == 0) rowptr[n] = ne;
}
__global__ void scatter_scan_kernel(const int* __restrict__ cnt, const int* __restrict__ boff,
                                    int* __restrict__ rowptr, int* __restrict__ cur, int n) {
    __shared__ int sh[512];
    int tid = threadIdx.x;
    int i = blockIdx.x * 512 + tid;
    int v = (i < n) ? cnt[i] : 0;
    sh[tid] = v;
    __syncthreads();
    for (int off = 1; off < 512; off <<= 1) {
        int t = (tid >= off) ? sh[tid - off] : 0;
        __syncthreads();
        sh[tid] += t;
        __syncthreads();
    }
    int excl = sh[tid] - v + boff[blockIdx.x];
    if (i < n) { rowptr[i] = excl; cur[i] = excl; }
}
__global__ void fill_kernel(const void* __restrict__ ei, int* __restrict__ cur,
                            int* __restrict__ eidx, int ne) {
    int i = blockIdx.x * blockDim.x + threadIdx.x;
    int is64 = g_is64;
    if (i < ne) {
        int s = edge_at(ei, i, is64);
        int d = edge_at(ei, (long long)ne + i, is64);
        eidx[atomicAdd(&cur[d], 1)] = s;
    }
}

// ---------------- conversions / transposes ----------------
__global__ void conv_bf16_kernel(const float* __restrict__ src, uint16_t* __restrict__ dst,
                                 int n4) {   // n4 = total/4
    int i = blockIdx.x * blockDim.x + threadIdx.x;
    if (i >= n4) return;
    float4 v = __ldg((const float4*)src + i);
    uint2 o;
    o.x = f2_to_bf2(v.x, v.y);
    o.y = f2_to_bf2(v.z, v.w);
    *((uint2*)dst + i) = o;
}
__global__ void transpose_w1(const float* __restrict__ Wl1, const float* __restrict__ Wr1,
                             float* __restrict__ W1t) {
    int i = blockIdx.x * blockDim.x + threadIdx.x;     // 128*256
    if (i < 128 * 256) {
        int nn = i >> 8, k = i & 255;
        W1t[i] = (k < 128) ? Wl1[k * 128 + nn] : Wr1[(k - 128) * 128 + nn];
    }
}
__global__ void transpose_w2(const float* __restrict__ Wl2, const float* __restrict__ Wr2,
                             float* __restrict__ W2t) {
    int i = blockIdx.x * blockDim.x + threadIdx.x;     // 128*128
    if (i < 128 * 128) {
        int nn = i >> 7, k = i & 127;
        W2t[i] = (nn < 64) ? Wl2[k * 64 + nn] : Wr2[k * 64 + (nn - 64)];
    }
}

// ---------------- gathers ----------------
// 128-wide bf16 rows (256B): lane holds 4 bf16 (uint2), accumulate f32.
__global__ void gather_mean128_bf16(const uint16_t* __restrict__ featb,
                                    const int* __restrict__ rowptr,
                                    const int* __restrict__ eidx,
                                    float* __restrict__ mean, int n) {
    int node = (blockIdx.x * blockDim.x + threadIdx.x) >> 5;
    if (node >= n) return;
    int lane = threadIdx.x & 31;
    int beg = rowptr[node], end = rowptr[node + 1];
    float4 acc = make_float4(0.f, 0.f, 0.f, 0.f);
    const uint2* fb = (const uint2*)featb;
    int j = beg;
    for (; j + 1 < end; j += 2) {
        int s0 = __ldg(&eidx[j]), s1 = __ldg(&eidx[j + 1]);
        uint2 v0 = __ldg(&fb[(size_t)s0 * 32 + lane]);
        uint2 v1 = __ldg(&fb[(size_t)s1 * 32 + lane]);
        float2 a0 = bf2_to_f2(v0.x), a1 = bf2_to_f2(v0.y);
        float2 b0 = bf2_to_f2(v1.x), b1 = bf2_to_f2(v1.y);
        acc.x += a0.x + b0.x; acc.y += a0.y + b0.y;
        acc.z += a1.x + b1.x; acc.w += a1.y + b1.y;
    }
    if (j < end) {
        int s0 = __ldg(&eidx[j]);
        uint2 v0 = __ldg(&fb[(size_t)s0 * 32 + lane]);
        float2 a0 = bf2_to_f2(v0.x), a1 = bf2_to_f2(v0.y);
        acc.x += a0.x; acc.y += a0.y; acc.z += a1.x; acc.w += a1.y;
    }
    float inv = 1.0f / fmaxf((float)(end - beg), 1.0f);
    acc.x *= inv; acc.y *= inv; acc.z *= inv; acc.w *= inv;
    ((float4*)mean)[(size_t)node * 32 + lane] = acc;
}

// 64-wide bf16 rows (128B): lane holds 2 bf16 (uint32). Fused final:
// out[node, 2*lane..] = sigmoid(mean + y2hi + bl2)
__global__ void gather_final64(const uint16_t* __restrict__ y2b,
                               const float* __restrict__ y2hi,
                               const float* __restrict__ bl2,
                               const int* __restrict__ rowptr,
                               const int* __restrict__ eidx,
                               float* __restrict__ out, int n) {
    int node = (blockIdx.x * blockDim.x + threadIdx.x) >> 5;
    if (node >= n) return;
    int lane = threadIdx.x & 31;
    int beg = rowptr[node], end = rowptr[node + 1];
    float2 acc = make_float2(0.f, 0.f);
    const uint32_t* fb = (const uint32_t*)y2b;
    int j = beg;
    for (; j + 1 < end; j += 2) {
        int s0 = __ldg(&eidx[j]), s1 = __ldg(&eidx[j + 1]);
        float2 v0 = bf2_to_f2(__ldg(&fb[(size_t)s0 * 32 + lane]));
        float2 v1 = bf2_to_f2(__ldg(&fb[(size_t)s1 * 32 + lane]));
        acc.x += v0.x + v1.x; acc.y += v0.y + v1.y;
    }
    if (j < end) {
        int s0 = __ldg(&eidx[j]);
        float2 v0 = bf2_to_f2(__ldg(&fb[(size_t)s0 * 32 + lane]));
        acc.x += v0.x; acc.y += v0.y;
    }
    float inv = 1.0f / fmaxf((float)(end - beg), 1.0f);
    float2 yh = *(const float2*)(y2hi + (size_t)node * 64 + lane * 2);
    float2 bb = *(const float2*)(bl2 + lane * 2);
    float2 o;
    o.x = 1.0f / (1.0f + __expf(-(acc.x * inv + yh.x + bb.x)));
    o.y = 1.0f / (1.0f + __expf(-(acc.y * inv + yh.y + bb.y)));
    *(float2*)(out + (size_t)node * 64 + lane * 2) = o;
}

// ---------------------------------------------------------------------------
// TF32 mma.sync GEMM: C[128-tile, 128] = A[*, KTOT] @ Wt^T  (Wt: [128, KTOT])
// Block 128x128, 8 warps 2(m)x4(n); warp tile 64x32; mma m16n8k8.
// EPI 1: relu(c+bias) -> f32 out[n,128]
// EPI 2: cols<64 -> bf16 outb[n,64]; cols>=64 -> f32 outhi[n,64]
// ---------------------------------------------------------------------------
template<int KTOT, int HAS_A1, int EPI>
__global__ void __launch_bounds__(256, 2)
mma_gemm(const float* __restrict__ A0, const float* __restrict__ A1,
         const float* __restrict__ Wt, const float* __restrict__ bias,
         float* __restrict__ out, uint16_t* __restrict__ outb,
         float* __restrict__ outhi, int n)
{
    constexpr int NCHUNK = KTOT / 32;
    __shared__ uint32_t As[128][36];
    __shared__ uint32_t Ws[128][36];

    const int tid  = threadIdx.x;
    const int wid  = tid >> 5;
    const int lane = tid & 31;
    const int wm   = wid & 1;
    const int wn   = wid >> 1;
    const int g    = lane >> 2;
    const int tg   = lane & 3;
    const int row0 = blockIdx.x * 128;

    float c[4][4][4];
#pragma unroll
    for (int mi = 0; mi < 4; mi++)
#pragma unroll
        for (int ni = 0; ni < 4; ni++)
#pragma unroll
            for (int j = 0; j < 4; j++) c[mi][ni][j] = 0.f;

#pragma unroll 1
    for (int ch = 0; ch < NCHUNK; ++ch) {
        const int kcol = ch * 32;
        const float* Asrc = A0;
        int kk = kcol;
        if (HAS_A1 && kcol >= 128) { Asrc = A1; kk = kcol - 128; }

#pragma unroll
        for (int i = tid; i < 1024; i += 256) {
            int r  = i >> 3;
            int k4 = (i & 7) * 4;
            int node = row0 + r;
            float4 av = make_float4(0.f, 0.f, 0.f, 0.f);
            if (node < n)
                av = *(const float4*)(Asrc + (size_t)node * 128 + kk + k4);
            uint4 at;
            at.x = f2tf32(av.x); at.y = f2tf32(av.y);
            at.z = f2tf32(av.z); at.w = f2tf32(av.w);
            *(uint4*)&As[r][k4] = at;

            float4 wv = *(const float4*)(Wt + (size_t)r * KTOT + kcol + k4);
            uint4 wt;
            wt.x = f2tf32(wv.x); wt.y = f2tf32(wv.y);
            wt.z = f2tf32(wv.z); wt.w = f2tf32(wv.w);
            *(uint4*)&Ws[r][k4] = wt;
        }
        __syncthreads();

#pragma unroll
        for (int ks = 0; ks < 4; ++ks) {
            const int k0 = ks * 8;
            uint32_t a[4][4];
#pragma unroll
            for (int mi = 0; mi < 4; mi++) {
                int mb = wm * 64 + mi * 16;
                a[mi][0] = As[mb + g][k0 + tg];
                a[mi][1] = As[mb + g + 8][k0 + tg];
                a[mi][2] = As[mb + g][k0 + tg + 4];
                a[mi][3] = As[mb + g + 8][k0 + tg + 4];
            }
#pragma unroll
            for (int ni = 0; ni < 4; ni++) {
                int nb = wn * 32 + ni * 8 + g;
                uint32_t b[2];
                b[0] = Ws[nb][k0 + tg];
                b[1] = Ws[nb][k0 + tg + 4];
#pragma unroll
                for (int mi = 0; mi < 4; mi++)
                    mma_tf32(c[mi][ni], a[mi], b);
            }
        }
        __syncthreads();
    }

#pragma unroll
    for (int mi = 0; mi < 4; mi++) {
#pragma unroll
        for (int half = 0; half < 2; half++) {
            int row = row0 + wm * 64 + mi * 16 + g + half * 8;
            if (row < n) {
#pragma unroll
                for (int ni = 0; ni < 4; ni++) {
                    int col = wn * 32 + ni * 8 + tg * 2;
                    float v0 = c[mi][ni][half * 2 + 0];
                    float v1 = c[mi][ni][half * 2 + 1];
                    if (EPI == 1) {
                        v0 = fmaxf(v0 + __ldg(&bias[col]), 0.f);
                        v1 = fmaxf(v1 + __ldg(&bias[col + 1]), 0.f);
                        *(float2*)(out + (size_t)row * 128 + col) = make_float2(v0, v1);
                    } else {
                        if (col < 64) {
                            *(uint32_t*)(outb + (size_t)row * 64 + col) = f2_to_bf2(v0, v1);
                        } else {
                            *(float2*)(outhi + (size_t)row * 64 + (col - 64)) =
                                make_float2(v0, v1);
                        }
                    }
                }
            }
        }
    }
}

// ---------------------------------------------------------------------------
extern "C" void kernel_launch(void* const* d_in, const int* in_sizes, int n_in,
                              void* d_out, int out_size) {
    const float* x   = (const float*)d_in[0];
    const void*  ei  = d_in[1];
    const float* Wl1 = (const float*)d_in[2];
    const float* bl1 = (const float*)d_in[3];
    const float* Wr1 = (const float*)d_in[4];
    const float* Wl2 = (const float*)d_in[5];
    const float* bl2 = (const float*)d_in[6];
    const float* Wr2 = (const float*)d_in[7];
    float* out = (float*)d_out;

    const int n  = in_sizes[0] / 128;   // 100000
    const int ne = in_sizes[1] / 2;     // 1600000

    float *mean, *h, *y2hi, *w1t, *w2t;
    uint16_t *xb, *y2b;
    int *cnt, *cur, *rowptr, *eidx, *bsum, *boff;
    cudaGetSymbolAddress((void**)&mean,   g_mean);
    cudaGetSymbolAddress((void**)&h,      g_h);
    cudaGetSymbolAddress((void**)&y2hi,   g_y2hi);
    cudaGetSymbolAddress((void**)&xb,     g_xb);
    cudaGetSymbolAddress((void**)&y2b,    g_y2b);
    cudaGetSymbolAddress((void**)&w1t,    g_w1t);
    cudaGetSymbolAddress((void**)&w2t,    g_w2t);
    cudaGetSymbolAddress((void**)&cnt,    g_cnt);
    cudaGetSymbolAddress((void**)&cur,    g_cur);
    cudaGetSymbolAddress((void**)&rowptr, g_rowptr);
    cudaGetSymbolAddress((void**)&eidx,   g_eidx);
    cudaGetSymbolAddress((void**)&bsum,   g_bsum);
    cudaGetSymbolAddress((void**)&boff,   g_boff);

    const int nscan = (n + 511) / 512;
    const int eblk  = (ne + 255) / 256;
    const int gblk  = (n + 7) / 8;
    const int mblk  = (n + 127) / 128;

    // ---- CSR build + conversions ----
    detect_kernel<<<1, 32>>>((const int*)ei);
    conv_bf16_kernel<<<(n * 32 + 255) / 256, 256>>>(x, xb, n * 32);
    transpose_w1<<<(128 * 256 + 255) / 256, 256>>>(Wl1, Wr1, w1t);
    transpose_w2<<<(128 * 128 + 255) / 256, 256>>>(Wl2, Wr2, w2t);
    zero_int_kernel<<<(n + 255) / 256, 256>>>(cnt, n);
    hist_kernel<<<eblk, 256>>>(ei, cnt, ne);
    blocksum_kernel<<<nscan, 512>>>(cnt, bsum, n);
    scanbsum_kernel<<<1, 256>>>(bsum, boff, rowptr, nscan, n, ne);
    scatter_scan_kernel<<<nscan, 512>>>(cnt, boff, rowptr, cur, n);
    fill_kernel<<<eblk, 256>>>(ei, cur, eidx, ne);

    // ---- layer 1 ----
    gather_mean128_bf16<<<gblk, 256>>>(xb, rowptr, eidx, mean, n);
    mma_gemm<256, 1, 1><<<mblk, 256>>>(mean, x, w1t, bl1, h, nullptr, nullptr, n);

    // ---- layer 2 ----
    mma_gemm<128, 0, 2><<<mblk, 256>>>(h, nullptr, w2t, nullptr, nullptr, y2b, y2hi, n);
    gather_final64<<<gblk, 256>>>(y2b, y2hi, bl2, rowptr, eidx, out, n);
}

// round 6
// speedup vs baseline: 2.9508x; 1.0525x over previous
#include <cuda_runtime.h>
#include <cuda_bf16.h>
#include <cstdint>
#include <math.h>

// ---------------------------------------------------------------------------
// GraphSAGE 2-layer. CSR gather-mean (bf16 payload, f32 accum, unroll-4) +
// TF32 mma.sync GEMMs with cp.async double-buffered mainloop (swizzled SMEM).
// ---------------------------------------------------------------------------

#define N_MAX 100000
#define E_MAX 1600000

__device__ float    g_mean[(size_t)N_MAX * 128];
__device__ float    g_h   [(size_t)N_MAX * 128];
__device__ float    g_y2hi[(size_t)N_MAX * 64];
__device__ uint16_t g_xb  [(size_t)N_MAX * 128];   // bf16 bits
__device__ uint16_t g_y2b [(size_t)N_MAX * 64];    // bf16 bits
__device__ float    g_w1t[128 * 256];              // [N=128, K=256] K-major, tf32-rounded
__device__ float    g_w2t[128 * 128];              // [N=128, K=128] K-major, tf32-rounded
__device__ int      g_cnt[N_MAX];
__device__ int      g_cur[N_MAX];
__device__ int      g_rowptr[N_MAX + 1];
__device__ int      g_eidx[E_MAX];
__device__ int      g_bsum[256];
__device__ int      g_boff[256];
__device__ int      g_is64;

// ---------------- helpers ----------------
__device__ __forceinline__ uint32_t f2tf32(float x) {
    uint32_t r;
    asm("cvt.rna.tf32.f32 %0, %1;" : "=r"(r) : "f"(x));
    return r;
}
__device__ __forceinline__ void mma_tf32(float (&c)[4], const uint32_t (&a)[4],
                                         const uint32_t (&b)[2]) {
    asm volatile(
        "mma.sync.aligned.m16n8k8.row.col.f32.tf32.tf32.f32 "
        "{%0,%1,%2,%3}, {%4,%5,%6,%7}, {%8,%9}, {%0,%1,%2,%3};"
        : "+f"(c[0]), "+f"(c[1]), "+f"(c[2]), "+f"(c[3])
        : "r"(a[0]), "r"(a[1]), "r"(a[2]), "r"(a[3]), "r"(b[0]), "r"(b[1]));
}
__device__ __forceinline__ float2 bf2_to_f2(uint32_t v) {
    __nv_bfloat162 b = *reinterpret_cast<__nv_bfloat162*>(&v);
    return __bfloat1622float2(b);
}
__device__ __forceinline__ uint32_t f2_to_bf2(float lo, float hi) {
    __nv_bfloat162 b = __floats2bfloat162_rn(lo, hi);
    return *reinterpret_cast<uint32_t*>(&b);
}
__device__ __forceinline__ uint32_t smem_u32(const void* p) {
    uint32_t a;
    asm("{ .reg .u64 t; cvta.to.shared.u64 t, %1; cvt.u32.u64 %0, t; }"
        : "=r"(a) : "l"(p));
    return a;
}
__device__ __forceinline__ void cp_async16(uint32_t smem, const void* g, int src_bytes) {
    asm volatile("cp.async.ca.shared.global [%0], [%1], 16, %2;"
                 :: "r"(smem), "l"(g), "r"(src_bytes) : "memory");
}
#define CP_COMMIT() asm volatile("cp.async.commit_group;" ::: "memory")
#define CP_WAIT0()  asm volatile("cp.async.wait_group 0;" ::: "memory")
#define CP_WAIT1()  asm volatile("cp.async.wait_group 1;" ::: "memory")

// swizzled word index inside a 128x32 f32 tile (conflict-free fragment reads,
// 16B-chunk compatible with cp.async)
__device__ __forceinline__ int swz(int r, int k) {
    return (r << 5) + ((k & ~3) ^ ((r & 7) << 2)) + (k & 3);
}

// ---------------- CSR build ----------------
__device__ __forceinline__ int edge_at(const void* ei, long long idx, int is64) {
    if (is64) return (int)((const long long*)ei)[idx];
    return ((const int*)ei)[idx];
}
__global__ void zero_int_kernel(int* p, int n) {
    int i = blockIdx.x * blockDim.x + threadIdx.x;
    if (i < n) p[i] = 0;
}
__global__ void hist_kernel(const void* __restrict__ ei, int* __restrict__ cnt, int ne) {
    int i = blockIdx.x * blockDim.x + threadIdx.x;
    int is64 = g_is64;
    if (i < ne) atomicAdd(&cnt[edge_at(ei, (long long)ne + i, is64)], 1);
}
__global__ void blocksum_kernel(const int* __restrict__ cnt, int* __restrict__ bsum, int n) {
    __shared__ int sh[512];
    int i = blockIdx.x * 512 + threadIdx.x;
    sh[threadIdx.x] = (i < n) ? cnt[i] : 0;
    __syncthreads();
    for (int off = 256; off > 0; off >>= 1) {
        if (threadIdx.x < off) sh[threadIdx.x] += sh[threadIdx.x + off];
        __syncthreads();
    }
    if (threadIdx.x == 0) bsum[blockIdx.x] = sh[0];
}
__global__ void scanbsum_kernel(const int* __restrict__ bsum, int* __restrict__ boff,
                                int* __restrict__ rowptr, int nb, int n, int ne) {
    __shared__ int sh[256];
    int tid = threadIdx.x;
    int v = (tid < nb) ? bsum[tid] : 0;
    sh[tid] = v;
    __syncthreads();
    for (int off = 1; off < 256; off <<= 1) {
        int t = (tid >= off) ? sh[tid - off] : 0;
        __syncthreads();
        sh[tid] += t;
        __syncthreads();
    }
    if (tid < nb) boff[tid] = sh[tid] - v;
    if (tid == 0) rowptr[n] = ne;
}
__global__ void scatter_scan_kernel(const int* __restrict__ cnt, const int* __restrict__ boff,
                                    int* __restrict__ rowptr, int* __restrict__ cur, int n) {
    __shared__ int sh[512];
    int tid = threadIdx.x;
    int i = blockIdx.x * 512 + tid;
    int v = (i < n) ? cnt[i] : 0;
    sh[tid] = v;
    __syncthreads();
    for (int off = 1; off < 512; off <<= 1) {
        int t = (tid >= off) ? sh[tid - off] : 0;
        __syncthreads();
        sh[tid] += t;
        __syncthreads();
    }
    int excl = sh[tid] - v + boff[blockIdx.x];
    if (i < n) { rowptr[i] = excl; cur[i] = excl; }
}
__global__ void fill_kernel(const void* __restrict__ ei, int* __restrict__ cur,
                            int* __restrict__ eidx, int ne) {
    int i = blockIdx.x * blockDim.x + threadIdx.x;
    int is64 = g_is64;
    if (i < ne) {
        int s = edge_at(ei, i, is64);
        int d = edge_at(ei, (long long)ne + i, is64);
        eidx[atomicAdd(&cur[d], 1)] = s;
    }
}

// ---------------- fused prep: x->bf16, W transposes (tf32-rounded), detect ----
__global__ void prep_kernel(const float* __restrict__ x, uint16_t* __restrict__ xb,
                            const float* __restrict__ Wl1, const float* __restrict__ Wr1,
                            float* __restrict__ W1t,
                            const float* __restrict__ Wl2, const float* __restrict__ Wr2,
                            float* __restrict__ W2t,
                            const int* __restrict__ ei, int n32) {
    int i = blockIdx.x * blockDim.x + threadIdx.x;
    if (i < n32) {
        float4 v = __ldg((const float4*)x + i);
        uint2 o;
        o.x = f2_to_bf2(v.x, v.y);
        o.y = f2_to_bf2(v.z, v.w);
        *((uint2*)xb + i) = o;
        return;
    }
    int j = i - n32;
    if (j < 128 * 256) {
        int nn = j >> 8, k = j & 255;
        float v = (k < 128) ? Wl1[k * 128 + nn] : Wr1[(k - 128) * 128 + nn];
        W1t[j] = __uint_as_float(f2tf32(v));
    } else if (j < 128 * 256 + 128 * 128) {
        int jj = j - 128 * 256;
        int nn = jj >> 7, k = jj & 127;
        float v = (nn < 64) ? Wl2[k * 64 + nn] : Wr2[k * 64 + (nn - 64)];
        W2t[jj] = __uint_as_float(f2tf32(v));
    } else if (j == 128 * 256 + 128 * 128) {
        int nz = 0;
        for (int q = 1; q < 256; q += 2) nz += (ei[q] != 0);
        g_is64 = (nz == 0) ? 1 : 0;
    }
}

// ---------------- gathers (unroll-4) ----------------
__global__ void gather_mean128_bf16(const uint16_t* __restrict__ featb,
                                    const int* __restrict__ rowptr,
                                    const int* __restrict__ eidx,
                                    float* __restrict__ mean, int n) {
    int node = (blockIdx.x * blockDim.x + threadIdx.x) >> 5;
    if (node >= n) return;
    int lane = threadIdx.x & 31;
    int beg = rowptr[node], end = rowptr[node + 1];
    float4 acc = make_float4(0.f, 0.f, 0.f, 0.f);
    const uint2* fb = (const uint2*)featb;
    int j = beg;
    for (; j + 3 < end; j += 4) {
        int s0 = __ldg(&eidx[j]),     s1 = __ldg(&eidx[j + 1]);
        int s2 = __ldg(&eidx[j + 2]), s3 = __ldg(&eidx[j + 3]);
        uint2 v0 = __ldg(&fb[(size_t)s0 * 32 + lane]);
        uint2 v1 = __ldg(&fb[(size_t)s1 * 32 + lane]);
        uint2 v2 = __ldg(&fb[(size_t)s2 * 32 + lane]);
        uint2 v3 = __ldg(&fb[(size_t)s3 * 32 + lane]);
        float2 a0 = bf2_to_f2(v0.x), a1 = bf2_to_f2(v0.y);
        float2 b0 = bf2_to_f2(v1.x), b1 = bf2_to_f2(v1.y);
        float2 c0 = bf2_to_f2(v2.x), c1 = bf2_to_f2(v2.y);
        float2 d0 = bf2_to_f2(v3.x), d1 = bf2_to_f2(v3.y);
        acc.x += (a0.x + b0.x) + (c0.x + d0.x);
        acc.y += (a0.y + b0.y) + (c0.y + d0.y);
        acc.z += (a1.x + b1.x) + (c1.x + d1.x);
        acc.w += (a1.y + b1.y) + (c1.y + d1.y);
    }
    for (; j < end; ++j) {
        int s0 = __ldg(&eidx[j]);
        uint2 v0 = __ldg(&fb[(size_t)s0 * 32 + lane]);
        float2 a0 = bf2_to_f2(v0.x), a1 = bf2_to_f2(v0.y);
        acc.x += a0.x; acc.y += a0.y; acc.z += a1.x; acc.w += a1.y;
    }
    float inv = 1.0f / fmaxf((float)(end - beg), 1.0f);
    acc.x *= inv; acc.y *= inv; acc.z *= inv; acc.w *= inv;
    ((float4*)mean)[(size_t)node * 32 + lane] = acc;
}

__global__ void gather_final64(const uint16_t* __restrict__ y2b,
                               const float* __restrict__ y2hi,
                               const float* __restrict__ bl2,
                               const int* __restrict__ rowptr,
                               const int* __restrict__ eidx,
                               float* __restrict__ out, int n) {
    int node = (blockIdx.x * blockDim.x + threadIdx.x) >> 5;
    if (node >= n) return;
    int lane = threadIdx.x & 31;
    int beg = rowptr[node], end = rowptr[node + 1];
    float2 acc = make_float2(0.f, 0.f);
    const uint32_t* fb = (const uint32_t*)y2b;
    int j = beg;
    for (; j + 3 < end; j += 4) {
        int s0 = __ldg(&eidx[j]),     s1 = __ldg(&eidx[j + 1]);
        int s2 = __ldg(&eidx[j + 2]), s3 = __ldg(&eidx[j + 3]);
        float2 v0 = bf2_to_f2(__ldg(&fb[(size_t)s0 * 32 + lane]));
        float2 v1 = bf2_to_f2(__ldg(&fb[(size_t)s1 * 32 + lane]));
        float2 v2 = bf2_to_f2(__ldg(&fb[(size_t)s2 * 32 + lane]));
        float2 v3 = bf2_to_f2(__ldg(&fb[(size_t)s3 * 32 + lane]));
        acc.x += (v0.x + v1.x) + (v2.x + v3.x);
        acc.y += (v0.y + v1.y) + (v2.y + v3.y);
    }
    for (; j < end; ++j) {
        int s0 = __ldg(&eidx[j]);
        float2 v0 = bf2_to_f2(__ldg(&fb[(size_t)s0 * 32 + lane]));
        acc.x += v0.x; acc.y += v0.y;
    }
    float inv = 1.0f / fmaxf((float)(end - beg), 1.0f);
    float2 yh = *(const float2*)(y2hi + (size_t)node * 64 + lane * 2);
    float2 bb = *(const float2*)(bl2 + lane * 2);
    float2 o;
    o.x = 1.0f / (1.0f + __expf(-(acc.x * inv + yh.x + bb.x)));
    o.y = 1.0f / (1.0f + __expf(-(acc.y * inv + yh.y + bb.y)));
    *(float2*)(out + (size_t)node * 64 + lane * 2) = o;
}

// ---------------------------------------------------------------------------
// TF32 mma.sync GEMM, cp.async double-buffered. C[128,128] = A[*,KTOT] @ Wt^T.
// Block 128x128, 8 warps 2(m)x4(n); warp tile 64x32; mma m16n8k8.
// SMEM: 2 stages x (A 16KB + W 16KB) = 64KB dynamic, XOR-swizzled.
// EPI 1: relu(c+bias) -> f32 out[n,128]
// EPI 2: cols<64 -> bf16 outb[n,64]; cols>=64 -> f32 outhi[n,64]
// ---------------------------------------------------------------------------
template<int KTOT, int HAS_A1, int EPI>
__global__ void __launch_bounds__(256, 2)
mma_gemm(const float* __restrict__ A0, const float* __restrict__ A1,
         const float* __restrict__ Wt, const float* __restrict__ bias,
         float* __restrict__ out, uint16_t* __restrict__ outb,
         float* __restrict__ outhi, int n)
{
    constexpr int NCHUNK = KTOT / 32;
    extern __shared__ float smem[];
    const uint32_t* As = (const uint32_t*)smem;           // [2][4096]
    const uint32_t* Ws = (const uint32_t*)(smem + 8192);  // [2][4096]

    const int tid  = threadIdx.x;
    const int wid  = tid >> 5;
    const int lane = tid & 31;
    const int wm   = wid & 1;
    const int wn   = wid >> 1;
    const int g    = lane >> 2;
    const int tg   = lane & 3;
    const int row0 = blockIdx.x * 128;

    const uint32_t as_b = smem_u32(smem);
    const uint32_t ws_b = as_b + 8192 * 4;

    float c[4][4][4];
#pragma unroll
    for (int mi = 0; mi < 4; mi++)
#pragma unroll
        for (int ni = 0; ni < 4; ni++)
#pragma unroll
            for (int j = 0; j < 4; j++) c[mi][ni][j] = 0.f;

    auto prefetch = [&](int ch, int stage) {
        const int kcol = ch * 32;
        const float* Asrc = A0;
        int kk = kcol;
        if (HAS_A1 && kcol >= 128) { Asrc = A1; kk = kcol - 128; }
        const uint32_t sofs = (uint32_t)stage << 14;   // 4096 words * 4 B
#pragma unroll
        for (int i = tid; i < 1024; i += 256) {
            int r = i >> 3, k4 = i & 7;
            uint32_t widx = (uint32_t)((r << 5) + ((k4 << 2) ^ ((r & 7) << 2)));
            int node = row0 + r;
            int ok = (node < n);
            const float* gA = Asrc + (size_t)(ok ? node : 0) * 128 + kk + (k4 << 2);
            cp_async16(as_b + sofs + widx * 4, gA, ok ? 16 : 0);
            const float* gW = Wt + (size_t)r * KTOT + kcol + (k4 << 2);
            cp_async16(ws_b + sofs + widx * 4, gW, 16);
        }
        CP_COMMIT();
    };

    prefetch(0, 0);

#pragma unroll 1
    for (int ch = 0; ch < NCHUNK; ++ch) {
        const int stage = ch & 1;
        if (ch + 1 < NCHUNK) {
            prefetch(ch + 1, stage ^ 1);
            CP_WAIT1();
        } else {
            CP_WAIT0();
        }
        __syncthreads();

        const uint32_t* Ab = As + (stage << 12);
        const uint32_t* Wb = Ws + (stage << 12);

#pragma unroll
        for (int ks = 0; ks < 4; ++ks) {
            const int k0 = ks * 8;
            uint32_t a[4][4];
#pragma unroll
            for (int mi = 0; mi < 4; mi++) {
                int r0 = wm * 64 + mi * 16 + g;
                a[mi][0] = Ab[swz(r0,     k0 + tg)];
                a[mi][1] = Ab[swz(r0 + 8, k0 + tg)];
                a[mi][2] = Ab[swz(r0,     k0 + tg + 4)];
                a[mi][3] = Ab[swz(r0 + 8, k0 + tg + 4)];
            }
#pragma unroll
            for (int ni = 0; ni < 4; ni++) {
                int nb = wn * 32 + ni * 8 + g;
                uint32_t b[2];
                b[0] = Wb[swz(nb, k0 + tg)];
                b[1] = Wb[swz(nb, k0 + tg + 4)];
#pragma unroll
                for (int mi = 0; mi < 4; mi++)
                    mma_tf32(c[mi][ni], a[mi], b);
            }
        }
        __syncthreads();
    }

#pragma unroll
    for (int mi = 0; mi < 4; mi++) {
#pragma unroll
        for (int half = 0; half < 2; half++) {
            int row = row0 + wm * 64 + mi * 16 + g + half * 8;
            if (row < n) {
#pragma unroll
                for (int ni = 0; ni < 4; ni++) {
                    int col = wn * 32 + ni * 8 + tg * 2;
                    float v0 = c[mi][ni][half * 2 + 0];
                    float v1 = c[mi][ni][half * 2 + 1];
                    if (EPI == 1) {
                        v0 = fmaxf(v0 + __ldg(&bias[col]), 0.f);
                        v1 = fmaxf(v1 + __ldg(&bias[col + 1]), 0.f);
                        *(float2*)(out + (size_t)row * 128 + col) = make_float2(v0, v1);
                    } else {
                        if (col < 64) {
                            *(uint32_t*)(outb + (size_t)row * 64 + col) = f2_to_bf2(v0, v1);
                        } else {
                            *(float2*)(outhi + (size_t)row * 64 + (col - 64)) =
                                make_float2(v0, v1);
                        }
                    }
                }
            }
        }
    }
}

// ---------------------------------------------------------------------------
extern "C" void kernel_launch(void* const* d_in, const int* in_sizes, int n_in,
                              void* d_out, int out_size) {
    const float* x   = (const float*)d_in[0];
    const void*  ei  = d_in[1];
    const float* Wl1 = (const float*)d_in[2];
    const float* bl1 = (const float*)d_in[3];
    const float* Wr1 = (const float*)d_in[4];
    const float* Wl2 = (const float*)d_in[5];
    const float* bl2 = (const float*)d_in[6];
    const float* Wr2 = (const float*)d_in[7];
    float* out = (float*)d_out;

    const int n  = in_sizes[0] / 128;   // 100000
    const int ne = in_sizes[1] / 2;     // 1600000

    float *mean, *h, *y2hi, *w1t, *w2t;
    uint16_t *xb, *y2b;
    int *cnt, *cur, *rowptr, *eidx, *bsum, *boff;
    cudaGetSymbolAddress((void**)&mean,   g_mean);
    cudaGetSymbolAddress((void**)&h,      g_h);
    cudaGetSymbolAddress((void**)&y2hi,   g_y2hi);
    cudaGetSymbolAddress((void**)&xb,     g_xb);
    cudaGetSymbolAddress((void**)&y2b,    g_y2b);
    cudaGetSymbolAddress((void**)&w1t,    g_w1t);
    cudaGetSymbolAddress((void**)&w2t,    g_w2t);
    cudaGetSymbolAddress((void**)&cnt,    g_cnt);
    cudaGetSymbolAddress((void**)&cur,    g_cur);
    cudaGetSymbolAddress((void**)&rowptr, g_rowptr);
    cudaGetSymbolAddress((void**)&eidx,   g_eidx);
    cudaGetSymbolAddress((void**)&bsum,   g_bsum);
    cudaGetSymbolAddress((void**)&boff,   g_boff);

    cudaFuncSetAttribute(mma_gemm<256, 1, 1>,
                         cudaFuncAttributeMaxDynamicSharedMemorySize, 65536);
    cudaFuncSetAttribute(mma_gemm<128, 0, 2>,
                         cudaFuncAttributeMaxDynamicSharedMemorySize, 65536);

    const int nscan = (n + 511) / 512;
    const int eblk  = (ne + 255) / 256;
    const int gblk  = (n + 7) / 8;
    const int mblk  = (n + 127) / 128;
    const int n32   = n * 32;
    const int pblk  = (n32 + 128 * 256 + 128 * 128 + 1 + 255) / 256;

    // ---- prep (conv + transposes + detect) and CSR build ----
    prep_kernel<<<pblk, 256>>>(x, xb, Wl1, Wr1, w1t, Wl2, Wr2, w2t, (const int*)ei, n32);
    zero_int_kernel<<<(n + 255) / 256, 256>>>(cnt, n);
    hist_kernel<<<eblk, 256>>>(ei, cnt, ne);
    blocksum_kernel<<<nscan, 512>>>(cnt, bsum, n);
    scanbsum_kernel<<<1, 256>>>(bsum, boff, rowptr, nscan, n, ne);
    scatter_scan_kernel<<<nscan, 512>>>(cnt, boff, rowptr, cur, n);
    fill_kernel<<<eblk, 256>>>(ei, cur, eidx, ne);

    // ---- layer 1 ----
    gather_mean128_bf16<<<gblk, 256>>>(xb, rowptr, eidx, mean, n);
    mma_gemm<256, 1, 1><<<mblk, 256, 65536>>>(mean, x, w1t, bl1, h, nullptr, nullptr, n);

    // ---- layer 2 ----
    mma_gemm<128, 0, 2><<<mblk, 256, 65536>>>(h, nullptr, w2t, nullptr, nullptr, y2b, y2hi, n);
    gather_final64<<<gblk, 256>>>(y2b, y2hi, bl2, rowptr, eidx, out, n);
}